// round 14
// baseline (speedup 1.0000x reference)
#include <cuda_runtime.h>
#include <cuda_fp16.h>
#include <cstdint>

// ---------------------------------------------------------------------------
// AnalogConv2d: 3x3 s1 p1, N=16 C=128 H=W=56 Cout=256, fp32 + bias.
// fp16 mma.sync.m16n8k16 (fp32 accum) implicit GEMM.
// R13 = R12 (256x128 CTA, 512 thr, 16 warps 4Mx4N, warp 64x32, 4-stage
// cp.async, CHK=64) + fine-grained LDS/MMA interleaving to overlap the L1
// and tensor pipes (R12 ncu showed them running additively):
//   - rolling A-fragment prefetch at mi granularity (af(next) issued under
//     the current mi's 4 MMAs)
//   - ldmB(ks+1) split into the mi==0 / mi==2 slots
// ---------------------------------------------------------------------------

#define CIN    128
#define HWD    56
#define LSP    3136
#define COUT   256
#define NIMG   16
#define LTOT   (NIMG * LSP)        // 50176
#define X4N    (NIMG * 16 * LSP)   // 802816 uint4 granules (8 ch each)
#define WT_N   (9 * 2 * 16 * 4 * 32 * 4)   // 147456
#define TM     256
#define TN     128
#define NCTA   (LTOT / TN)         // 392
#define NCHUNK 18                  // 9 taps * 2 (CHK=64 channels)
#define STAGES 4
#define A_ST_B 32768u              // 256*64*2
#define B_ST_B 16384u              // 128*64*2
#define STG_B  (A_ST_B + B_ST_B)   // 49152
#define SMEMB  (STAGES * STG_B)    // 196608 (192KB)

// Weights fragment-major fp16 pairs: [tap][ck2][mf16][ks4][lane32][4regs]
__device__ __align__(256) uint32_t g_Wh[WT_N];
// x packed 8-channel fp16 granules: [img][c8(16)][l(3136)], one uint4 each
__device__ __align__(256) uint4 g_X4[X4N];

__device__ __forceinline__ void cpa16(uint32_t d, const void* s) {
    asm volatile("cp.async.cg.shared.global [%0], [%1], 16;" :: "r"(d), "l"(s));
}
__device__ __forceinline__ void cpa16z(uint32_t d, const void* s, uint32_t sz) {
    asm volatile("cp.async.cg.shared.global [%0], [%1], 16, %2;"
                 :: "r"(d), "l"(s), "r"(sz));
}
__device__ __forceinline__ void mma_f16(float* d, const uint32_t* a,
                                        const uint32_t* b) {
    asm volatile(
        "mma.sync.aligned.m16n8k16.row.col.f32.f16.f16.f32 "
        "{%0,%1,%2,%3}, {%4,%5,%6,%7}, {%8,%9}, {%0,%1,%2,%3};"
        : "+f"(d[0]), "+f"(d[1]), "+f"(d[2]), "+f"(d[3])
        : "r"(a[0]), "r"(a[1]), "r"(a[2]), "r"(a[3]), "r"(b[0]), "r"(b[1]));
}
__device__ __forceinline__ void ldmx4(uint32_t& r0, uint32_t& r1,
                                      uint32_t& r2, uint32_t& r3, uint32_t a) {
    asm volatile("ldmatrix.sync.aligned.m8n8.x4.shared.b16 {%0,%1,%2,%3}, [%4];"
                 : "=r"(r0), "=r"(r1), "=r"(r2), "=r"(r3) : "r"(a));
}

// ---------------------------------------------------------------------------
// Fused transform: x -> g_X4 (8ch granules), w -> g_Wh fragment-major.
// ---------------------------------------------------------------------------
__global__ void transform_kernel(const float* __restrict__ x,
                                 const float* __restrict__ w) {
    int i = blockIdx.x * blockDim.x + threadIdx.x;
    if (i < X4N) {
        int l  = i % LSP;
        int t  = i / LSP;
        int c8 = t & 15;
        int im = t >> 4;
        const float* p = x + ((size_t)im * CIN + c8 * 8) * LSP + l;
        uint32_t wds[4];
        #pragma unroll
        for (int j = 0; j < 4; ++j) {
            __half2 h = __floats2half2_rn(p[(size_t)(2 * j) * LSP],
                                          p[(size_t)(2 * j + 1) * LSP]);
            wds[j] = *reinterpret_cast<uint32_t*>(&h);
        }
        uint4 v = { wds[0], wds[1], wds[2], wds[3] };
        g_X4[i] = v;
    } else {
        int idx = i - X4N;
        if (idx >= WT_N) return;
        int r    = idx & 3;
        int lane = (idx >> 2) & 31;
        int ks   = (idx >> 7) & 3;
        int mf   = (idx >> 9) & 15;
        int ck   = (idx >> 13) & 1;
        int tap  = idx >> 14;
        int g = lane >> 2, tig = lane & 3;
        int co = mf * 16 + g + 8 * (r & 1);
        int c  = ck * 64 + ks * 16 + 2 * tig + 8 * (r >> 1);
        __half2 v = __floats2half2_rn(w[(co * CIN + c) * 9 + tap],
                                      w[(co * CIN + c + 1) * 9 + tap]);
        g_Wh[idx] = *reinterpret_cast<uint32_t*>(&v);
    }
}

// ---------------------------------------------------------------------------
__global__ void __launch_bounds__(512, 1)
conv_mma_kernel(const float* __restrict__ bias,
                float* __restrict__ out) {
    extern __shared__ float smem[];
    uint32_t sb;
    asm("{ .reg .u64 t; cvta.to.shared.u64 t, %1; cvt.u32.u64 %0, t; }"
        : "=r"(sb) : "l"(smem));

    const int tid  = threadIdx.x;
    const int wid  = tid >> 5;
    const int lane = tid & 31;
    const int wm   = wid >> 2;        // 0..3 : 64-row Cout band
    const int wn   = wid & 3;         // 0..3 : 32-col pos band

    const int l0 = blockIdx.x * TN;

    // ---- B gather setup: thread -> (pos, jb); 2 x 16B granules each ----
    const int pos = tid & 127;
    const int jb  = (tid >> 7) * 2;    // granule base within chunk: 0,2,4,6
    const int l   = l0 + pos;
    const int img = l / LSP;
    const int rl  = l - img * LSP;
    const int oh  = rl / HWD;
    const int ow  = rl - oh * HWD;
    const uint4* xb = g_X4 + (size_t)img * 16 * LSP;
    const uint32_t hsw3 = (uint32_t)pos & 7u;
    const uint32_t bdst_row = (uint32_t)pos * 32u;   // words per B row

    // ---- ldmatrix lane address precompute ----
    const int lt = lane >> 3;          // tile 0..3 within one ldmx4
    const int lr = lane & 7;           // row within m8 tile
    const int lh = lt & 1;             // k-half
    const uint32_t lanebase =
        (uint32_t)(wn * 32 + (lt >> 1) * 8 + lr) * 128u;   // bytes

    float acc[4][4][4];
    #pragma unroll
    for (int mi = 0; mi < 4; ++mi)
        #pragma unroll
        for (int ni = 0; ni < 4; ++ni)
            #pragma unroll
            for (int r2 = 0; r2 < 4; ++r2)
                acc[mi][ni][r2] = 0.0f;

    auto prefetch = [&](int q, int s) {
        const int tap = q >> 1;
        const int ck  = q & 1;
        const int ki  = tap / 3, kj = tap - ki * 3;
        const uint32_t sbase = sb + (uint32_t)s * STG_B;
        // A: 32KB contiguous fragment-major, 4 x 16B per thread
        const uint32_t* asrc = g_Wh + (((size_t)(tap * 2 + ck)) << 13);
        #pragma unroll
        for (int i = 0; i < 4; ++i)
            cpa16(sbase + (uint32_t)(i * 512 + tid) * 16u,
                  asrc + (i * 512 + tid) * 4);
        // B: 2 x 16B granules (8 channels each), coalesced across pos
        const int ih = oh + ki - 1, iw = ow + kj - 1;
        const bool valid = ((unsigned)ih < HWD) & ((unsigned)iw < HWD);
        const uint4* src = valid
            ? (xb + (size_t)(ck * 8 + jb) * LSP + ih * HWD + iw)
            : g_X4;
        const uint32_t sz = valid ? 16u : 0u;
        const uint32_t bb = sbase + A_ST_B;
        #pragma unroll
        for (int i = 0; i < 2; ++i) {
            uint32_t gi = (uint32_t)(jb + i);
            cpa16z(bb + (bdst_row + ((gi ^ hsw3) << 2)) * 4u,
                   src + (size_t)i * LSP, sz);
        }
    };

    auto compute = [&](int s) {
        const uint4* A4 = (const uint4*)(smem + s * (STG_B / 4));
        const uint32_t bB = sb + (uint32_t)s * STG_B + A_ST_B + lanebase;

        uint32_t bf[2][4][2];
        // one ldmx4 (p = 0 or 1) of B fragments for a given ks into buffer b
        auto ldmB_p = [&](int ks, int b, int p) {
            const uint32_t goff = (uint32_t)(((2 * ks + lh) ^ lr) << 4);
            ldmx4(bf[b][p * 2][0], bf[b][p * 2][1],
                  bf[b][p * 2 + 1][0], bf[b][p * 2 + 1][1],
                  bB + (uint32_t)p * 2048u + goff);
        };

        // warm up: B frags for ks=0, A frag for (ks=0, mi=0)
        ldmB_p(0, 0, 0);
        ldmB_p(0, 0, 1);
        uint4 a_cur = A4[((wm * 4 + 0) * 4 + 0) * 32 + lane];

        #pragma unroll
        for (int ks = 0; ks < 4; ++ks) {
            const int cur = ks & 1;
            #pragma unroll
            for (int mi = 0; mi < 4; ++mi) {
                // spread next-ks B loads into mi==0 / mi==2 slots
                if (mi == 0 && ks < 3) ldmB_p(ks + 1, cur ^ 1, 0);
                if (mi == 2 && ks < 3) ldmB_p(ks + 1, cur ^ 1, 1);
                // rolling A prefetch: issue LDS for the NEXT fragment, then
                // do this fragment's MMAs (LDS flows under the tensor work)
                uint4 a_nxt;
                {
                    int f = ks * 4 + mi + 1;          // next fragment 1..16
                    int nk = (f >> 2) & 3;            // f==16 wraps harmlessly
                    int nm = f & 3;
                    a_nxt = A4[((wm * 4 + nm) * 4 + nk) * 32 + lane];
                }
                uint32_t a_[4] = { a_cur.x, a_cur.y, a_cur.z, a_cur.w };
                #pragma unroll
                for (int ni = 0; ni < 4; ++ni)
                    mma_f16(acc[mi][ni], a_, bf[cur][ni]);
                a_cur = a_nxt;
            }
        }
    };

    // ---- 4-stage pipeline, one sync per chunk ----
    #pragma unroll
    for (int s = 0; s < STAGES - 1; ++s) {
        prefetch(s, s);
        asm volatile("cp.async.commit_group;" ::: "memory");
    }
    #pragma unroll 1
    for (int q = 0; q < NCHUNK; ++q) {
        asm volatile("cp.async.wait_group %0;" :: "n"(STAGES - 2) : "memory");
        __syncthreads();   // stage q&3 visible; slot (q+3)&3 free to refill
        if (q + STAGES - 1 < NCHUNK)
            prefetch(q + STAGES - 1, (q + STAGES - 1) & (STAGES - 1));
        asm volatile("cp.async.commit_group;" ::: "memory");
        compute(q & (STAGES - 1));
    }

    // ---- epilogue: +bias, float2 stores ----
    const int g   = lane >> 2;
    const int tig = lane & 3;
    const int co_base = wm * 64 + g;
    float bv[4][2];
    #pragma unroll
    for (int mi = 0; mi < 4; ++mi) {
        bv[mi][0] = bias[co_base + mi * 16];
        bv[mi][1] = bias[co_base + mi * 16 + 8];
    }
    #pragma unroll
    for (int ni = 0; ni < 4; ++ni) {
        const int le  = l0 + wn * 32 + ni * 8 + 2 * tig;
        const int im2 = le / LSP;
        const int rle = le - im2 * LSP;
        float* ob = out + (size_t)im2 * COUT * LSP + rle;
        #pragma unroll
        for (int mi = 0; mi < 4; ++mi) {
            #pragma unroll
            for (int h = 0; h < 2; ++h) {
                const int co = co_base + mi * 16 + h * 8;
                float2 v;
                v.x = acc[mi][ni][h * 2 + 0] + bv[mi][h];
                v.y = acc[mi][ni][h * 2 + 1] + bv[mi][h];
                *reinterpret_cast<float2*>(ob + (size_t)co * LSP) = v;
            }
        }
    }
}

// ---------------------------------------------------------------------------
extern "C" void kernel_launch(void* const* d_in, const int* in_sizes, int n_in,
                              void* d_out, int out_size) {
    const float* x    = (const float*)d_in[0];
    const float* w    = (const float*)d_in[1];
    const float* bias = (const float*)d_in[2];
    float* out = (float*)d_out;

    cudaFuncSetAttribute(conv_mma_kernel,
                         cudaFuncAttributeMaxDynamicSharedMemorySize, SMEMB);

    transform_kernel<<<(X4N + WT_N + 255) / 256, 256>>>(x, w);
    conv_mma_kernel<<<NCTA, 512, SMEMB>>>(bias, out);
}